// round 16
// baseline (speedup 1.0000x reference)
#include <cuda_runtime.h>
#include <cuda_fp16.h>
#include <cstdint>
#include <cstddef>

// Problem constants
#define L_SEQ  2048
#define BATCH  32
#define DIM    512
#define NLAY   4
#define MTOT   (L_SEQ*BATCH)   // 65536
#define NTOT   (3*DIM)         // 1536
#define PSH    ((size_t)MTOT*DIM)       // halves per u plane
#define HSTRIDE 16384                   // halves per t-step in fragment space
#define L2E    1.4426950408889634f

// ---------------- device-global scratch ------------------------------------
__device__ __half g_hh[(size_t)MTOT*DIM];                // 64 MB  h/x, frag order
__device__ __half g_Wh[(size_t)NLAY*NTOT*DIM];           // 6.3 MB W fp16 frag order
__device__ __half g_uh[2*PSH];                           // 128 MB u0,u1 fp16 planar
__device__ __half g_u2h[(size_t)MTOT*DIM];               // 64 MB  u2 fp16 frag order
__device__ __half g_ch[(size_t)MTOT*DIM];                // 64 MB  c fp16 frag order
__device__ uint32_t g_mb[BATCH*(L_SEQ/32)];              // mask bits, b-major
__device__ uint32_t g_mbt[L_SEQ];                        // mask bits, t-major (bit=b)

// ---------------- helpers ---------------------------------------------------
__device__ __forceinline__ uint32_t smem_u32(const void* p) {
    uint32_t a;
    asm("{ .reg .u64 t; cvta.to.shared.u64 t, %1; cvt.u32.u64 %0, t; }"
        : "=r"(a) : "l"(p));
    return a;
}
__device__ __forceinline__ void cp16(uint32_t dst, const void* src) {
    asm volatile("cp.async.cg.shared.global [%0], [%1], 16;\n"
                 :: "r"(dst), "l"(src));
}
__device__ __forceinline__ void cp4(uint32_t dst, const void* src) {
    asm volatile("cp.async.ca.shared.global [%0], [%1], 4;\n"
                 :: "r"(dst), "l"(src));
}
#define CP_COMMIT() asm volatile("cp.async.commit_group;")
#define CP_WAIT(n)  asm volatile("cp.async.wait_group %0;" :: "n"(n) : "memory")

__device__ __forceinline__ float ex2f(float x) {
    float r; asm("ex2.approx.f32 %0, %1;" : "=f"(r) : "f"(x)); return r;
}
__device__ __forceinline__ float rcpf(float x) {
    float r; asm("rcp.approx.f32 %0, %1;" : "=f"(r) : "f"(x)); return r;
}
__device__ __forceinline__ void lds128(uint32_t* r, uint32_t a) {
    asm volatile("ld.shared.v4.b32 {%0,%1,%2,%3}, [%4];"
                 : "=r"(r[0]), "=r"(r[1]), "=r"(r[2]), "=r"(r[3]) : "r"(a));
}
__device__ __forceinline__ void lds64(uint32_t* r, uint32_t a) {
    asm volatile("ld.shared.v2.b32 {%0,%1}, [%2];"
                 : "=r"(r[0]), "=r"(r[1]) : "r"(a));
}
__device__ __forceinline__ void mma_f16(float* d, const uint32_t* a, const uint32_t* b) {
    asm volatile("mma.sync.aligned.m16n8k16.row.col.f32.f16.f16.f32 "
                 "{%0,%1,%2,%3}, {%4,%5,%6,%7}, {%8,%9}, {%0,%1,%2,%3};"
                 : "+f"(d[0]), "+f"(d[1]), "+f"(d[2]), "+f"(d[3])
                 : "r"(a[0]), "r"(a[1]), "r"(a[2]), "r"(a[3]),
                   "r"(b[0]), "r"(b[1]));
}

// fragment-order addressing (half-element index), m16n8k16
__device__ __forceinline__ size_t fragA16(int m, int k) {
    size_t blk = (size_t)(m >> 4) * 32 + (k >> 4);
    int lane = ((m & 7) << 2) | ((k & 7) >> 1);
    int reg  = ((m >> 3) & 1) + 2 * ((k >> 3) & 1);
    return blk * 256 + (size_t)((lane * 4 + reg) * 2 + (k & 1));
}
__device__ __forceinline__ size_t fragB16(int n, int k) {
    size_t blk = (size_t)(n >> 3) * 32 + (k >> 4);
    int lane = ((n & 7) << 2) | ((k & 7) >> 1);
    int reg  = (k >> 3) & 1;
    return blk * 128 + (size_t)((lane * 2 + reg) * 2 + (k & 1));
}

// ---------------- GEMM -------------------------------------------------------
#define MT 128
#define NT 128
#define KC 64
#define NCHUNK (DIM/KC)      // 8
#define OFF_B  16384
#define STAGE  32768
#define NSTAGE 3
#define SMEM_TOTAL (NSTAGE*STAGE)   // 98304

__device__ __forceinline__ void load_stage(uint32_t st, int mb0, int nb0, int kb0,
                                           const __half* __restrict__ A,
                                           const __half* __restrict__ B, int tid)
{
    #pragma unroll
    for (int it = 0; it < 4; it++) {       // A: [m16 8][kb 4][512B]
        int i = tid + it * 256;
        int mbl = i >> 7, rem = i & 127;
        int kbl = rem >> 5, cc = rem & 31;
        const __half* src = A + ((size_t)(mb0 + mbl) * 32 + (kb0 + kbl)) * 256 + cc * 8;
        cp16(st + (uint32_t)i * 16u, src);
    }
    #pragma unroll
    for (int it = 0; it < 4; it++) {       // B: [n8 16][kb 4][256B]
        int i = tid + it * 256;
        int nbl = i >> 6, rem = i & 63;
        int kbl = rem >> 4, cc = rem & 15;
        const __half* src = B + ((size_t)(nb0 + nbl) * 32 + (kb0 + kbl)) * 128 + cc * 8;
        cp16(st + OFF_B + (uint32_t)i * 16u, src);
    }
    CP_COMMIT();
}

struct FragT { uint32_t a[2][4]; uint32_t b[8][2]; };

__device__ __forceinline__ void load_frag(FragT& f, uint32_t st, int kb,
                                          int wm, int wn, int lane)
{
    #pragma unroll
    for (int mt = 0; mt < 2; mt++)
        lds128(f.a[mt], st + (uint32_t)((((wm * 2 + mt) * 4 + kb) * 512) + lane * 16));
    #pragma unroll
    for (int nt = 0; nt < 8; nt++)
        lds64(f.b[nt], st + OFF_B +
              (uint32_t)((((wn * 8 + nt) * 4 + kb) * 256) + lane * 8));
}
__device__ __forceinline__ void mma_all(float acc[2][8][4], const FragT& f)
{
    #pragma unroll
    for (int mt = 0; mt < 2; mt++)
        #pragma unroll
        for (int nt = 0; nt < 8; nt++)
            mma_f16(acc[mt][nt], f.a[mt], f.b[nt]);
}

__device__ __forceinline__ void store_u2h(int m, int k, float a, float b)
{
    size_t off = ((size_t)(m >> 4) * 32 + (k >> 4)) * 256
               + (size_t)(((((m & 7) << 2) | ((k & 7) >> 1)) * 4
                           + (((m >> 3) & 1) + 2 * ((k >> 3) & 1))) * 2);
    *(__half2*)(g_u2h + off) = __floats2half2_rn(a, b);
}

__global__ void __launch_bounds__(256, 2)
gemm_kernel(int layer, int n_tiles, int tile_base)
{
    extern __shared__ __align__(1024) char smem[];
    uint32_t sb = smem_u32(smem);
    int tid  = threadIdx.x;
    int wid  = tid >> 5, lane = tid & 31;
    int wm   = wid & 3;
    int wn   = wid >> 2;
    int m0   = (blockIdx.x / n_tiles) * MT;
    int n0   = (tile_base + blockIdx.x % n_tiles) * NT;
    int mb0  = m0 >> 4;
    int nb0  = n0 >> 3;

    const __half* A = g_hh;
    const __half* B = g_Wh + (size_t)layer * NTOT * DIM;

    float acc[2][8][4];
    #pragma unroll
    for (int i = 0; i < 2; i++)
        #pragma unroll
        for (int j = 0; j < 8; j++)
            #pragma unroll
            for (int q = 0; q < 4; q++) acc[i][j][q] = 0.f;

    load_stage(sb,         mb0, nb0, 0, A, B, tid);
    load_stage(sb + STAGE, mb0, nb0, 4, A, B, tid);

    for (int chunk = 0; chunk < NCHUNK; ++chunk) {
        if (chunk < NCHUNK - 1) CP_WAIT(1);
        else                    CP_WAIT(0);
        __syncthreads();

        if (chunk + 2 < NCHUNK)
            load_stage(sb + (uint32_t)((chunk + 2) % NSTAGE) * STAGE,
                       mb0, nb0, (chunk + 2) * 4, A, B, tid);

        uint32_t st = sb + (uint32_t)(chunk % NSTAGE) * STAGE;
        FragT f;
        #pragma unroll
        for (int kb = 0; kb < 4; kb++) {
            load_frag(f, st, kb, wm, wn, lane);
            mma_all(acc, f);
        }
    }

    // epilogue
    int plane = n0 >> 9;
    int nc0   = n0 & 511;
    int rbase = lane >> 2;
    int cbase = (lane & 3) * 2;
    if (plane < 2) {   // u0/u1 -> fp16 planar: offset m*512 + n
        __half* Up = g_uh + (size_t)plane * PSH;
        #pragma unroll
        for (int mt = 0; mt < 2; mt++) {
            int mrow = m0 + wm * 32 + mt * 16 + rbase;
            #pragma unroll
            for (int nt = 0; nt < 8; nt++) {
                int ncol = nc0 + wn * 64 + nt * 8 + cbase;
                *(__half2*)(Up + (size_t)mrow * DIM + ncol) =
                    __floats2half2_rn(acc[mt][nt][0], acc[mt][nt][1]);
                *(__half2*)(Up + (size_t)(mrow + 8) * DIM + ncol) =
                    __floats2half2_rn(acc[mt][nt][2], acc[mt][nt][3]);
            }
        }
    } else {  // u2 -> fp16 fragment order
        #pragma unroll
        for (int mt = 0; mt < 2; mt++) {
            int mrow = m0 + wm * 32 + mt * 16 + rbase;
            #pragma unroll
            for (int nt = 0; nt < 8; nt++) {
                int k = nc0 + wn * 64 + nt * 8 + cbase;
                store_u2h(mrow,     k, acc[mt][nt][0], acc[mt][nt][1]);
                store_u2h(mrow + 8, k, acc[mt][nt][2], acc[mt][nt][3]);
            }
        }
    }
}

// ---------------- pre-passes -------------------------------------------------
__global__ void __launch_bounds__(128)
split_x_kernel(const float* __restrict__ x)
{
    int e = blockIdx.x;                  // e = b*L + t
    int b = e >> 11, t = e & (L_SEQ - 1);
    int m = t * 32 + b;
    float4 v = ((const float4*)(x + (size_t)e * DIM))[threadIdx.x];
    int d0 = threadIdx.x * 4;
    g_hh[fragA16(m, d0 + 0)] = __float2half_rn(v.x);
    g_hh[fragA16(m, d0 + 1)] = __float2half_rn(v.y);
    g_hh[fragA16(m, d0 + 2)] = __float2half_rn(v.z);
    g_hh[fragA16(m, d0 + 3)] = __float2half_rn(v.w);
}

__global__ void __launch_bounds__(256)
split_w_kernel(const float* __restrict__ W)
{
    int o = blockIdx.x * 256 + threadIdx.x;   // [l][k][n] linear
    int l = o / (DIM * NTOT);
    int rem = o - l * (DIM * NTOT);
    int k = rem / NTOT, n = rem - k * NTOT;
    float w = W[o];
    g_Wh[(size_t)l * NTOT * DIM + fragB16(n, k)] = __float2half_rn(w);
}

__global__ void __launch_bounds__(64)
pack_mask_kernel(const int* __restrict__ mask)
{
    int b = blockIdx.x, w = threadIdx.x;   // grid 32, block 64
    uint32_t bits = 0;
    #pragma unroll 8
    for (int i = 0; i < 32; i++)
        bits |= (mask[b * L_SEQ + w * 32 + i] != 0 ? 1u : 0u) << i;
    g_mb[b * (L_SEQ/32) + w] = bits;
}

__global__ void __launch_bounds__(128)
pack_mask_t_kernel(const int* __restrict__ mask)
{
    int t = blockIdx.x * 128 + threadIdx.x;   // 2048 threads
    uint32_t bits = 0;
    #pragma unroll 8
    for (int b = 0; b < 32; b++)
        bits |= (mask[b * L_SEQ + t] != 0 ? 1u : 0u) << b;
    g_mbt[t] = bits;
}

// ---------------- c-scan (serial chain only) ---------------------------------
// smem per step: 512 B = 128 u0-halves | 128 u1-halves. One cp4/thread/step.
// Cross-thread smem staging => wait + __syncthreads before reading, and a
// barrier after compute before a buffer is refilled (WAR).
#define RB 16
#define NB (L_SEQ/RB)        // 128
#define RSMEM (2*RB*512)     // 16384 bytes

__device__ __forceinline__ void cs_issue(uint32_t sbase, int s, int t0, int tid,
                                         const __half* __restrict__ psrc)
{
    #pragma unroll
    for (int j = 0; j < RB; j++) {
        uint32_t dst = sbase + (uint32_t)((s * RB + j) * 512 + tid * 4);
        cp4(dst, psrc + (size_t)(t0 + j) * HSTRIDE);
    }
    CP_COMMIT();
}

template<bool LAST>
__device__ __forceinline__ void cs_compute(const __half* __restrict__ su,
    int s, int tid, int t0, uint32_t mw, float& c,
    float vfl, float nlbf, __half* __restrict__ hc)
{
    int shb = t0 & 31;
    #pragma unroll
    for (int j = 0; j < RB; j++) {
        const __half* sp = su + (s * RB + j) * 256 + tid;
        float u0 = __half2float(sp[0]);
        float u1 = __half2float(sp[128]);
        float ulb = fmaf(-L2E, u1, nlbf);      // off-chain
        bool pad = ((mw >> (shb + j)) & 1u) == 0u;
        float cd = c - u0;                      // parallel with sigmoid
        float e  = ex2f(fmaf(vfl, c, ulb));    // e = exp(-z)
        float f  = rcpf(1.f + e);
        float cn = fmaf(f, cd, u0);
        c = pad ? c : cn;
        if (!LAST)
            hc[(size_t)(t0 + j) * HSTRIDE] = __float2half_rn(c);
    }
}

template<bool LAST>
__global__ void __launch_bounds__(128)
cscan_kernel(const float* __restrict__ state, const float* __restrict__ vc,
             const float* __restrict__ bias, float* __restrict__ out, int layer)
{
    extern __shared__ __half su[];       // [2][RB][256 halves]
    int tid = threadIdx.x;
    int g = blockIdx.x * 128 + tid;
    int b = g >> 9, d = g & (DIM - 1);
    float vf = vc[layer * 2 * DIM + d];
    float bf = bias[layer * 2 * DIM + d];
    float vfl  = -L2E * vf;
    float nlbf = -L2E * bf;
    float c  = state[layer * DIM + d];

    // loader role: tid<64 -> u0 words, tid>=64 -> u1 words (2 halves each)
    const __half* psrc = g_uh + (size_t)(tid >> 6) * PSH
                       + (size_t)blockIdx.x * 128 + 2 * (tid & 63);
    __half* hc = g_ch + fragA16(b, d);
    const uint32_t* mb = g_mb + b * (L_SEQ/32);
    uint32_t sbase = smem_u32(su);

    cs_issue(sbase, 0, 0, tid, psrc);
    uint32_t mw = mb[0];

    for (int blk = 0; blk < NB; blk += 2) {
        int t0 = blk * RB;
        cs_issue(sbase, 1, t0 + RB, tid, psrc);
        int nw = (blk >> 1) + 1;
        uint32_t mwn = mb[nw < (L_SEQ/32) ? nw : (L_SEQ/32) - 1];

        CP_WAIT(1);
        __syncthreads();                       // s0 data visible to all
        cs_compute<LAST>(su, 0, tid, t0, mw, c, vfl, nlbf, hc);
        __syncthreads();                       // all done reading s0

        if (blk + 2 < NB) {
            cs_issue(sbase, 0, t0 + 2 * RB, tid, psrc);
            CP_WAIT(1);
        } else {
            CP_WAIT(0);
        }
        __syncthreads();                       // s1 data visible to all
        cs_compute<LAST>(su, 1, tid, t0 + RB, mw, c, vfl, nlbf, hc);
        __syncthreads();                       // all done reading s1
        mw = mwn;
    }

    if (layer == 0) out[g] = c;
    else            out[g] += c;
}

// ---------------- h-update (fully parallel) ----------------------------------
__global__ void __launch_bounds__(256)
hupdate_kernel(const float* __restrict__ vc, const float* __restrict__ bias,
               int layer)
{
    int g = blockIdx.x * 256 + threadIdx.x;   // chunk id (8 halves)
    int blk  = g >> 5;
    int lane = g & 31;
    int m16 = blk >> 5, k16 = blk & 31;
    int t = m16 >> 1;
    uint32_t mbits = g_mbt[t];
    int mA = m16 * 16 + ((lane >> 2) & 7);
    int mB = mA + 8;
    bool padA = ((mbits >> (mA & 31)) & 1u) == 0u;
    bool padB = ((mbits >> (mB & 31)) & 1u) == 0u;
    int k0 = k16 * 16 + (lane & 3) * 2;

    const float* vr = vc   + layer * 2 * DIM + DIM;
    const float* br = bias + layer * 2 * DIM + DIM;
    float2 vr0 = *(const float2*)(vr + k0);
    float2 vr8 = *(const float2*)(vr + k0 + 8);
    float2 br0 = *(const float2*)(br + k0);
    float2 br8 = *(const float2*)(br + k0 + 8);

    size_t off = (size_t)blk * 256 + (size_t)lane * 8;
    uint4 cu = *(const uint4*)(g_ch  + off);
    uint4 xu = *(const uint4*)(g_hh  + off);
    uint4 uu = *(const uint4*)(g_u2h + off);
    const __half2* ch = (const __half2*)&cu;
    const __half2* xh = (const __half2*)&xu;
    const __half2* uh = (const __half2*)&uu;

    float vrv[4] = {vr0.x, vr0.y, vr8.x, vr8.y};
    float brv[4] = {br0.x, br0.y, br8.x, br8.y};
    bool  padp[4] = {padA, padB, padA, padB};

    __half2 res[4];
    #pragma unroll
    for (int p = 0; p < 4; p++) {
        float2 cf = __half22float2(ch[p]);
        float2 xf = __half22float2(xh[p]);
        float2 uf = __half22float2(uh[p]);
        int kk = (p >> 1) * 2;
        float z0 = fmaf(vrv[kk],   cf.x, uf.x + brv[kk]);
        float z1 = fmaf(vrv[kk+1], cf.y, uf.y + brv[kk+1]);
        float r0 = rcpf(1.f + ex2f(-L2E * z0));
        float r1 = rcpf(1.f + ex2f(-L2E * z1));
        float h0 = fmaf(r0, cf.x - xf.x, xf.x);
        float h1 = fmaf(r1, cf.y - xf.y, xf.y);
        if (padp[p]) { h0 = 0.f; h1 = 0.f; }
        res[p] = __floats2half2_rn(h0, h1);
    }
    uint4 ro;
    __half2* rh = (__half2*)&ro;
    rh[0] = res[0]; rh[1] = res[1]; rh[2] = res[2]; rh[3] = res[3];
    *(uint4*)(g_hh + off) = ro;
}

// ---------------- launch -----------------------------------------------------
extern "C" void kernel_launch(void* const* d_in, const int* in_sizes, int n_in,
                              void* d_out, int out_size)
{
    const float* x     = (const float*)d_in[0];
    const int*   mask  = (const int*)  d_in[1];
    const float* state = (const float*)d_in[2];
    const float* W     = (const float*)d_in[3];
    const float* vc    = (const float*)d_in[4];
    const float* bias  = (const float*)d_in[5];
    float* out = (float*)d_out;

    cudaFuncSetAttribute(gemm_kernel,
                         cudaFuncAttributeMaxDynamicSharedMemorySize, SMEM_TOTAL);

    split_x_kernel<<<BATCH * L_SEQ, 128>>>(x);
    split_w_kernel<<<(NLAY * NTOT * DIM) / 256, 256>>>(W);
    pack_mask_kernel<<<BATCH, 64>>>(mask);
    pack_mask_t_kernel<<<L_SEQ / 128, 128>>>(mask);

    for (int l = 0; l < NLAY; l++) {
        if (l == NLAY - 1) {
            // last layer: only u0/u1 needed
            gemm_kernel<<<(MTOT / MT) * 8, 256, SMEM_TOTAL>>>(l, 8, 0);
            cscan_kernel<true><<<(BATCH * DIM) / 128, 128, RSMEM>>>(state, vc, bias, out, l);
        } else {
            gemm_kernel<<<(MTOT / MT) * 12, 256, SMEM_TOTAL>>>(l, 12, 0);
            cscan_kernel<false><<<(BATCH * DIM) / 128, 128, RSMEM>>>(state, vc, bias, out, l);
            hupdate_kernel<<<(int)((size_t)MTOT * DIM / 8 / 256), 256>>>(vc, bias, l);
        }
    }
    (void)in_sizes; (void)n_in; (void)out_size;
}

// round 17
// speedup vs baseline: 1.0373x; 1.0373x over previous
#include <cuda_runtime.h>
#include <cuda_fp16.h>
#include <cstdint>
#include <cstddef>

// Problem constants
#define L_SEQ  2048
#define BATCH  32
#define DIM    512
#define NLAY   4
#define MTOT   (L_SEQ*BATCH)   // 65536
#define NTOT   (3*DIM)         // 1536
#define PSH    ((size_t)MTOT*DIM)       // halves per u plane
#define HSTRIDE 16384                   // halves per t-step in fragment space
#define L2E    1.4426950408889634f

// ---------------- device-global scratch ------------------------------------
__device__ __half g_hh[(size_t)MTOT*DIM];                // 64 MB  h/x, frag order
__device__ __half g_Wh[(size_t)NLAY*NTOT*DIM];           // 6.3 MB W fp16 frag order
__device__ __half g_uh[2*PSH];                           // 128 MB u0,u1 fp16 planar
__device__ __half g_u2h[(size_t)MTOT*DIM];               // 64 MB  u2 fp16 frag order
__device__ __half g_ch[(size_t)MTOT*DIM];                // 64 MB  c fp16 frag order
__device__ uint32_t g_mb[BATCH*(L_SEQ/32)];              // mask bits, b-major
__device__ uint32_t g_mbt[L_SEQ];                        // mask bits, t-major (bit=b)

// ---------------- helpers ---------------------------------------------------
__device__ __forceinline__ uint32_t smem_u32(const void* p) {
    uint32_t a;
    asm("{ .reg .u64 t; cvta.to.shared.u64 t, %1; cvt.u32.u64 %0, t; }"
        : "=r"(a) : "l"(p));
    return a;
}
__device__ __forceinline__ void cp16(uint32_t dst, const void* src) {
    asm volatile("cp.async.cg.shared.global [%0], [%1], 16;\n"
                 :: "r"(dst), "l"(src));
}
__device__ __forceinline__ void cp4(uint32_t dst, const void* src) {
    asm volatile("cp.async.ca.shared.global [%0], [%1], 4;\n"
                 :: "r"(dst), "l"(src));
}
#define CP_COMMIT() asm volatile("cp.async.commit_group;")
#define CP_WAIT(n)  asm volatile("cp.async.wait_group %0;" :: "n"(n) : "memory")

__device__ __forceinline__ float ex2f(float x) {
    float r; asm("ex2.approx.f32 %0, %1;" : "=f"(r) : "f"(x)); return r;
}
__device__ __forceinline__ float rcpf(float x) {
    float r; asm("rcp.approx.f32 %0, %1;" : "=f"(r) : "f"(x)); return r;
}
__device__ __forceinline__ void lds128(uint32_t* r, uint32_t a) {
    asm volatile("ld.shared.v4.b32 {%0,%1,%2,%3}, [%4];"
                 : "=r"(r[0]), "=r"(r[1]), "=r"(r[2]), "=r"(r[3]) : "r"(a));
}
__device__ __forceinline__ void lds64(uint32_t* r, uint32_t a) {
    asm volatile("ld.shared.v2.b32 {%0,%1}, [%2];"
                 : "=r"(r[0]), "=r"(r[1]) : "r"(a));
}
__device__ __forceinline__ void mma_f16(float* d, const uint32_t* a, const uint32_t* b) {
    asm volatile("mma.sync.aligned.m16n8k16.row.col.f32.f16.f16.f32 "
                 "{%0,%1,%2,%3}, {%4,%5,%6,%7}, {%8,%9}, {%0,%1,%2,%3};"
                 : "+f"(d[0]), "+f"(d[1]), "+f"(d[2]), "+f"(d[3])
                 : "r"(a[0]), "r"(a[1]), "r"(a[2]), "r"(a[3]),
                   "r"(b[0]), "r"(b[1]));
}

// fragment-order addressing (half-element index), m16n8k16
__device__ __forceinline__ size_t fragA16(int m, int k) {
    size_t blk = (size_t)(m >> 4) * 32 + (k >> 4);
    int lane = ((m & 7) << 2) | ((k & 7) >> 1);
    int reg  = ((m >> 3) & 1) + 2 * ((k >> 3) & 1);
    return blk * 256 + (size_t)((lane * 4 + reg) * 2 + (k & 1));
}
__device__ __forceinline__ size_t fragB16(int n, int k) {
    size_t blk = (size_t)(n >> 3) * 32 + (k >> 4);
    int lane = ((n & 7) << 2) | ((k & 7) >> 1);
    int reg  = (k >> 3) & 1;
    return blk * 128 + (size_t)((lane * 2 + reg) * 2 + (k & 1));
}

// ---------------- GEMM body --------------------------------------------------
#define MT 128
#define NT 128
#define KC 64
#define NCHUNK (DIM/KC)      // 8
#define OFF_B  16384
#define STAGE  32768
#define NSTAGE 3
#define SMEM_TOTAL (NSTAGE*STAGE)   // 98304

__device__ __forceinline__ void load_stage(uint32_t st, int mb0, int nb0, int kb0,
                                           const __half* __restrict__ A,
                                           const __half* __restrict__ B, int tid)
{
    #pragma unroll
    for (int it = 0; it < 4; it++) {       // A: [m16 8][kb 4][512B]
        int i = tid + it * 256;
        int mbl = i >> 7, rem = i & 127;
        int kbl = rem >> 5, cc = rem & 31;
        const __half* src = A + ((size_t)(mb0 + mbl) * 32 + (kb0 + kbl)) * 256 + cc * 8;
        cp16(st + (uint32_t)i * 16u, src);
    }
    #pragma unroll
    for (int it = 0; it < 4; it++) {       // B: [n8 16][kb 4][256B]
        int i = tid + it * 256;
        int nbl = i >> 6, rem = i & 63;
        int kbl = rem >> 4, cc = rem & 15;
        const __half* src = B + ((size_t)(nb0 + nbl) * 32 + (kb0 + kbl)) * 128 + cc * 8;
        cp16(st + OFF_B + (uint32_t)i * 16u, src);
    }
    CP_COMMIT();
}

struct FragT { uint32_t a[2][4]; uint32_t b[8][2]; };

__device__ __forceinline__ void load_frag(FragT& f, uint32_t st, int kb,
                                          int wm, int wn, int lane)
{
    #pragma unroll
    for (int mt = 0; mt < 2; mt++)
        lds128(f.a[mt], st + (uint32_t)((((wm * 2 + mt) * 4 + kb) * 512) + lane * 16));
    #pragma unroll
    for (int nt = 0; nt < 8; nt++)
        lds64(f.b[nt], st + OFF_B +
              (uint32_t)((((wn * 8 + nt) * 4 + kb) * 256) + lane * 8));
}
__device__ __forceinline__ void mma_all(float acc[2][8][4], const FragT& f)
{
    #pragma unroll
    for (int mt = 0; mt < 2; mt++)
        #pragma unroll
        for (int nt = 0; nt < 8; nt++)
            mma_f16(acc[mt][nt], f.a[mt], f.b[nt]);
}

__device__ __forceinline__ void store_u2h(int m, int k, float a, float b)
{
    size_t off = ((size_t)(m >> 4) * 32 + (k >> 4)) * 256
               + (size_t)(((((m & 7) << 2) | ((k & 7) >> 1)) * 4
                           + (((m >> 3) & 1) + 2 * ((k >> 3) & 1))) * 2);
    *(__half2*)(g_u2h + off) = __floats2half2_rn(a, b);
}

__device__ void gemm_body(int layer, int m0, int n0, char* smem)
{
    uint32_t sb = smem_u32(smem);
    int tid  = threadIdx.x;
    int wid  = tid >> 5, lane = tid & 31;
    int wm   = wid & 3;
    int wn   = wid >> 2;
    int mb0  = m0 >> 4;
    int nb0  = n0 >> 3;

    const __half* A = g_hh;
    const __half* B = g_Wh + (size_t)layer * NTOT * DIM;

    float acc[2][8][4];
    #pragma unroll
    for (int i = 0; i < 2; i++)
        #pragma unroll
        for (int j = 0; j < 8; j++)
            #pragma unroll
            for (int q = 0; q < 4; q++) acc[i][j][q] = 0.f;

    load_stage(sb,         mb0, nb0, 0, A, B, tid);
    load_stage(sb + STAGE, mb0, nb0, 4, A, B, tid);

    for (int chunk = 0; chunk < NCHUNK; ++chunk) {
        if (chunk < NCHUNK - 1) CP_WAIT(1);
        else                    CP_WAIT(0);
        __syncthreads();

        if (chunk + 2 < NCHUNK)
            load_stage(sb + (uint32_t)((chunk + 2) % NSTAGE) * STAGE,
                       mb0, nb0, (chunk + 2) * 4, A, B, tid);

        uint32_t st = sb + (uint32_t)(chunk % NSTAGE) * STAGE;
        FragT f;
        #pragma unroll
        for (int kb = 0; kb < 4; kb++) {
            load_frag(f, st, kb, wm, wn, lane);
            mma_all(acc, f);
        }
    }

    // epilogue
    int plane = n0 >> 9;
    int nc0   = n0 & 511;
    int rbase = lane >> 2;
    int cbase = (lane & 3) * 2;
    if (plane < 2) {   // u0/u1 -> fp16 planar: offset m*512 + n
        __half* Up = g_uh + (size_t)plane * PSH;
        #pragma unroll
        for (int mt = 0; mt < 2; mt++) {
            int mrow = m0 + wm * 32 + mt * 16 + rbase;
            #pragma unroll
            for (int nt = 0; nt < 8; nt++) {
                int ncol = nc0 + wn * 64 + nt * 8 + cbase;
                *(__half2*)(Up + (size_t)mrow * DIM + ncol) =
                    __floats2half2_rn(acc[mt][nt][0], acc[mt][nt][1]);
                *(__half2*)(Up + (size_t)(mrow + 8) * DIM + ncol) =
                    __floats2half2_rn(acc[mt][nt][2], acc[mt][nt][3]);
            }
        }
    } else {  // u2 -> fp16 fragment order
        #pragma unroll
        for (int mt = 0; mt < 2; mt++) {
            int mrow = m0 + wm * 32 + mt * 16 + rbase;
            #pragma unroll
            for (int nt = 0; nt < 8; nt++) {
                int k = nc0 + wn * 64 + nt * 8 + cbase;
                store_u2h(mrow,     k, acc[mt][nt][0], acc[mt][nt][1]);
                store_u2h(mrow + 8, k, acc[mt][nt][2], acc[mt][nt][3]);
            }
        }
    }
}

__global__ void __launch_bounds__(256, 2)
gemm_kernel(int layer, int n_tiles, int tile_base)
{
    extern __shared__ __align__(1024) char smem[];
    int m0 = (blockIdx.x / n_tiles) * MT;
    int n0 = (tile_base + blockIdx.x % n_tiles) * NT;
    gemm_body(layer, m0, n0, smem);
}

// ---------------- c-scan body ------------------------------------------------
// 128 active threads (tid<128); extra threads participate in barriers only.
// smem per step: 512 B = 128 u0-halves | 128 u1-halves. One cp4/thread/step.
#define RB 16
#define NB (L_SEQ/RB)        // 128
#define RSMEM (2*RB*512)     // 16384 bytes (subset of gemm smem)

__device__ __forceinline__ void cs_issue(uint32_t sbase, int s, int t0, int tid,
                                         const __half* __restrict__ psrc, bool act)
{
    if (act) {
        #pragma unroll
        for (int j = 0; j < RB; j++) {
            uint32_t dst = sbase + (uint32_t)((s * RB + j) * 512 + tid * 4);
            cp4(dst, psrc + (size_t)(t0 + j) * HSTRIDE);
        }
    }
    CP_COMMIT();
}

template<bool LAST>
__device__ __forceinline__ void cs_compute(const __half* __restrict__ su,
    int s, int tid, int t0, uint32_t mw, float& c,
    float vfl, float nlbf, __half* __restrict__ hc)
{
    int shb = t0 & 31;
    #pragma unroll
    for (int j = 0; j < RB; j++) {
        const __half* sp = su + (s * RB + j) * 256 + tid;
        float u0 = __half2float(sp[0]);
        float u1 = __half2float(sp[128]);
        float ulb = fmaf(-L2E, u1, nlbf);      // off-chain
        bool pad = ((mw >> (shb + j)) & 1u) == 0u;
        float cd = c - u0;                      // parallel with sigmoid
        float e  = ex2f(fmaf(vfl, c, ulb));    // e = exp(-z)
        float f  = rcpf(1.f + e);
        float cn = fmaf(f, cd, u0);
        c = pad ? c : cn;
        if (!LAST)
            hc[(size_t)(t0 + j) * HSTRIDE] = __float2half_rn(c);
    }
}

template<bool LAST>
__device__ void cscan_body(int bx, const float* __restrict__ state,
                           const float* __restrict__ vc,
                           const float* __restrict__ bias,
                           float* __restrict__ out, int layer, char* smem)
{
    __half* su = (__half*)smem;          // [2][RB][256 halves]
    int tid = threadIdx.x;
    bool act = tid < 128;
    int g = bx * 128 + (tid & 127);
    int b = g >> 9, d = g & (DIM - 1);
    float vf = vc[layer * 2 * DIM + d];
    float bf = bias[layer * 2 * DIM + d];
    float vfl  = -L2E * vf;
    float nlbf = -L2E * bf;
    float c  = state[layer * DIM + d];

    // loader role (active threads): tid<64 -> u0 words, 64..127 -> u1 words
    const __half* psrc = g_uh + (size_t)((tid >> 6) & 1) * PSH
                       + (size_t)bx * 128 + 2 * (tid & 63);
    __half* hc = g_ch + fragA16(b, d);
    const uint32_t* mb = g_mb + b * (L_SEQ/32);
    uint32_t sbase = smem_u32(su);

    cs_issue(sbase, 0, 0, tid, psrc, act);
    uint32_t mw = mb[0];

    for (int blk = 0; blk < NB; blk += 2) {
        int t0 = blk * RB;
        cs_issue(sbase, 1, t0 + RB, tid, psrc, act);
        int nw = (blk >> 1) + 1;
        uint32_t mwn = mb[nw < (L_SEQ/32) ? nw : (L_SEQ/32) - 1];

        CP_WAIT(1);
        __syncthreads();                       // s0 data visible to all
        if (act) cs_compute<LAST>(su, 0, tid, t0, mw, c, vfl, nlbf, hc);
        __syncthreads();                       // all done reading s0

        if (blk + 2 < NB) {
            cs_issue(sbase, 0, t0 + 2 * RB, tid, psrc, act);
            CP_WAIT(1);
        } else {
            CP_WAIT(0);
        }
        __syncthreads();                       // s1 data visible to all
        if (act) cs_compute<LAST>(su, 1, tid, t0 + RB, mw, c, vfl, nlbf, hc);
        __syncthreads();                       // all done reading s1
        mw = mwn;
    }

    if (act) {
        if (layer == 0) out[g] = c;
        else            out[g] += c;
    }
}

// standalone cscan (last layer)
template<bool LAST>
__global__ void __launch_bounds__(128)
cscan_kernel(const float* __restrict__ state, const float* __restrict__ vc,
             const float* __restrict__ bias, float* __restrict__ out, int layer)
{
    extern __shared__ __align__(1024) char smem[];
    cscan_body<LAST>(blockIdx.x, state, vc, bias, out, layer, smem);
}

// ---------------- fused: cscan (blocks 0..127) || u2-gemm (blocks 128..) ----
#define NCS 128
__global__ void __launch_bounds__(256, 2)
fused_kernel(const float* __restrict__ state, const float* __restrict__ vc,
             const float* __restrict__ bias, float* __restrict__ out, int layer)
{
    extern __shared__ __align__(1024) char smem[];
    if (blockIdx.x < NCS) {
        cscan_body<false>(blockIdx.x, state, vc, bias, out, layer, smem);
    } else {
        int bidx = blockIdx.x - NCS;
        int m0 = (bidx >> 2) * MT;
        int n0 = (8 + (bidx & 3)) * NT;     // u2 tiles
        gemm_body(layer, m0, n0, smem);
    }
}

// ---------------- pre-passes -------------------------------------------------
__global__ void __launch_bounds__(128)
split_x_kernel(const float* __restrict__ x)
{
    int e = blockIdx.x;                  // e = b*L + t
    int b = e >> 11, t = e & (L_SEQ - 1);
    int m = t * 32 + b;
    float4 v = ((const float4*)(x + (size_t)e * DIM))[threadIdx.x];
    int d0 = threadIdx.x * 4;
    g_hh[fragA16(m, d0 + 0)] = __float2half_rn(v.x);
    g_hh[fragA16(m, d0 + 1)] = __float2half_rn(v.y);
    g_hh[fragA16(m, d0 + 2)] = __float2half_rn(v.z);
    g_hh[fragA16(m, d0 + 3)] = __float2half_rn(v.w);
}

__global__ void __launch_bounds__(256)
split_w_kernel(const float* __restrict__ W)
{
    int o = blockIdx.x * 256 + threadIdx.x;   // [l][k][n] linear
    int l = o / (DIM * NTOT);
    int rem = o - l * (DIM * NTOT);
    int k = rem / NTOT, n = rem - k * NTOT;
    float w = W[o];
    g_Wh[(size_t)l * NTOT * DIM + fragB16(n, k)] = __float2half_rn(w);
}

__global__ void __launch_bounds__(64)
pack_mask_kernel(const int* __restrict__ mask)
{
    int b = blockIdx.x, w = threadIdx.x;   // grid 32, block 64
    uint32_t bits = 0;
    #pragma unroll 8
    for (int i = 0; i < 32; i++)
        bits |= (mask[b * L_SEQ + w * 32 + i] != 0 ? 1u : 0u) << i;
    g_mb[b * (L_SEQ/32) + w] = bits;
}

__global__ void __launch_bounds__(128)
pack_mask_t_kernel(const int* __restrict__ mask)
{
    int t = blockIdx.x * 128 + threadIdx.x;   // 2048 threads
    uint32_t bits = 0;
    #pragma unroll 8
    for (int b = 0; b < 32; b++)
        bits |= (mask[b * L_SEQ + t] != 0 ? 1u : 0u) << b;
    g_mbt[t] = bits;
}

// ---------------- h-update (fully parallel) ----------------------------------
__global__ void __launch_bounds__(256)
hupdate_kernel(const float* __restrict__ vc, const float* __restrict__ bias,
               int layer)
{
    int g = blockIdx.x * 256 + threadIdx.x;   // chunk id (8 halves)
    int blk  = g >> 5;
    int lane = g & 31;
    int m16 = blk >> 5, k16 = blk & 31;
    int t = m16 >> 1;
    uint32_t mbits = g_mbt[t];
    int mA = m16 * 16 + ((lane >> 2) & 7);
    int mB = mA + 8;
    bool padA = ((mbits >> (mA & 31)) & 1u) == 0u;
    bool padB = ((mbits >> (mB & 31)) & 1u) == 0u;
    int k0 = k16 * 16 + (lane & 3) * 2;

    const float* vr = vc   + layer * 2 * DIM + DIM;
    const float* br = bias + layer * 2 * DIM + DIM;
    float2 vr0 = *(const float2*)(vr + k0);
    float2 vr8 = *(const float2*)(vr + k0 + 8);
    float2 br0 = *(const float2*)(br + k0);
    float2 br8 = *(const float2*)(br + k0 + 8);

    size_t off = (size_t)blk * 256 + (size_t)lane * 8;
    uint4 cu = *(const uint4*)(g_ch  + off);
    uint4 xu = *(const uint4*)(g_hh  + off);
    uint4 uu = *(const uint4*)(g_u2h + off);
    const __half2* ch = (const __half2*)&cu;
    const __half2* xh = (const __half2*)&xu;
    const __half2* uh = (const __half2*)&uu;

    float vrv[4] = {vr0.x, vr0.y, vr8.x, vr8.y};
    float brv[4] = {br0.x, br0.y, br8.x, br8.y};
    bool  padp[4] = {padA, padB, padA, padB};

    __half2 res[4];
    #pragma unroll
    for (int p = 0; p < 4; p++) {
        float2 cf = __half22float2(ch[p]);
        float2 xf = __half22float2(xh[p]);
        float2 uf = __half22float2(uh[p]);
        int kk = (p >> 1) * 2;
        float z0 = fmaf(vrv[kk],   cf.x, uf.x + brv[kk]);
        float z1 = fmaf(vrv[kk+1], cf.y, uf.y + brv[kk+1]);
        float r0 = rcpf(1.f + ex2f(-L2E * z0));
        float r1 = rcpf(1.f + ex2f(-L2E * z1));
        float h0 = fmaf(r0, cf.x - xf.x, xf.x);
        float h1 = fmaf(r1, cf.y - xf.y, xf.y);
        if (padp[p]) { h0 = 0.f; h1 = 0.f; }
        res[p] = __floats2half2_rn(h0, h1);
    }
    uint4 ro;
    __half2* rh = (__half2*)&ro;
    rh[0] = res[0]; rh[1] = res[1]; rh[2] = res[2]; rh[3] = res[3];
    *(uint4*)(g_hh + off) = ro;
}

// ---------------- launch -----------------------------------------------------
extern "C" void kernel_launch(void* const* d_in, const int* in_sizes, int n_in,
                              void* d_out, int out_size)
{
    const float* x     = (const float*)d_in[0];
    const int*   mask  = (const int*)  d_in[1];
    const float* state = (const float*)d_in[2];
    const float* W     = (const float*)d_in[3];
    const float* vc    = (const float*)d_in[4];
    const float* bias  = (const float*)d_in[5];
    float* out = (float*)d_out;

    cudaFuncSetAttribute(gemm_kernel,
                         cudaFuncAttributeMaxDynamicSharedMemorySize, SMEM_TOTAL);
    cudaFuncSetAttribute(fused_kernel,
                         cudaFuncAttributeMaxDynamicSharedMemorySize, SMEM_TOTAL);

    split_x_kernel<<<BATCH * L_SEQ, 128>>>(x);
    split_w_kernel<<<(NLAY * NTOT * DIM) / 256, 256>>>(W);
    pack_mask_kernel<<<BATCH, 64>>>(mask);
    pack_mask_t_kernel<<<L_SEQ / 128, 128>>>(mask);

    for (int l = 0; l < NLAY; l++) {
        // u0/u1 tiles (8 N-tiles)
        gemm_kernel<<<(MTOT / MT) * 8, 256, SMEM_TOTAL>>>(l, 8, 0);
        if (l == NLAY - 1) {
            cscan_kernel<true><<<(BATCH * DIM) / 128, 128, RSMEM>>>(state, vc, bias, out, l);
        } else {
            // fused: cscan (blocks 0..127) || u2-gemm (blocks 128..2175)
            fused_kernel<<<NCS + (MTOT / MT) * 4, 256, SMEM_TOTAL>>>(state, vc, bias, out, l);
            hupdate_kernel<<<(int)((size_t)MTOT * DIM / 8 / 256), 256>>>(vc, bias, l);
        }
    }
    (void)in_sizes; (void)n_in; (void)out_size;
}